// round 8
// baseline (speedup 1.0000x reference)
#include <cuda_runtime.h>
#include <cstdint>

#define NN 100000
#define EE 1600000
#define HH 128
#define H3 384
#define LL 3

// ---------------- scratch (static device globals; no allocation) ----------------
__device__ __align__(256) float g_m[(size_t)NN * HH];     // m = x @ W[l]
__device__ __align__(256) float g_agg[(size_t)NN * HH];   // scatter-add target
__device__ __align__(256) float g_gi[(size_t)NN * H3];    // agg @ w_ih^T + b_ih
__device__ __align__(256) float g_gh[(size_t)NN * H3];    // x   @ w_hh^T + b_hh
__device__ __align__(256) float g_x[(size_t)NN * HH];     // hidden state ping buffer
__device__ __align__(256) float g_wt_ih[(size_t)HH * H3]; // w_ih transposed -> [128][384]
__device__ __align__(256) float g_wt_hh[(size_t)HH * H3]; // w_hh transposed -> [128][384]
__device__ int g_idx64;                                    // 1 if edge_index buffer is int64

// ---------------- detect edge_index dtype ----------------
// int64 positive values < 2^31 have zero high words at odd 32-bit positions.
// int32 data has real indices there (all-zero over 2048 samples ~ impossible).
__global__ void detect_idx_kernel(const int* __restrict__ ei32) {
    int bad = 0;
    for (int i = threadIdx.x; i < 4096; i += blockDim.x) {
        if ((i & 1) && ei32[i] != 0) bad = 1;
    }
    bad = __syncthreads_or(bad);
    if (threadIdx.x == 0) g_idx64 = bad ? 0 : 1;
}

// ---------------- transpose [384][128] -> [128][384] ----------------
__global__ void transpose_w_kernel(const float* __restrict__ w, float* __restrict__ wt) {
    int i = blockIdx.x * blockDim.x + threadIdx.x;
    if (i < H3 * HH) {
        int j = i / HH;   // 0..383
        int k = i % HH;   // 0..127
        wt[k * H3 + j] = w[i];
    }
}

// ---------------- zero buffer (float4) ----------------
__global__ void zero_kernel(float4* __restrict__ p, int n4) {
    int i = blockIdx.x * blockDim.x + threadIdx.x;
    if (i < n4) p[i] = make_float4(0.f, 0.f, 0.f, 0.f);
}

// ---------------- tiled fp32 GEMM: C[nrows x 128k] = A[nrows x 128] @ B[128 x ncols] (+bias) ----
#define BM 64
#define KC 32
__global__ __launch_bounds__(256) void gemm_bias_kernel(
    const float* __restrict__ A, const float* __restrict__ B,
    const float* __restrict__ bias, float* __restrict__ C,
    int nrows, int ncols)
{
    __shared__ __align__(16) float Ast[KC][BM + 4];
    __shared__ __align__(16) float Bs[KC][128];

    const int tid = threadIdx.x;          // 256 threads
    const int tx  = tid & 15;             // cols tx*8 .. tx*8+7
    const int ty  = tid >> 4;             // rows ty*4 .. ty*4+3
    const int row0 = blockIdx.x * BM;
    const int col0 = blockIdx.y * 128;

    float acc[4][8];
#pragma unroll
    for (int i = 0; i < 4; i++)
#pragma unroll
        for (int j = 0; j < 8; j++) acc[i][j] = 0.f;

    const int ka = tid & 31;
    const int ra = tid >> 5;

    for (int kc = 0; kc < HH; kc += KC) {
#pragma unroll
        for (int i = 0; i < 8; i++) {
            int r = ra + i * 8;
            int grow = row0 + r;
            float v = (grow < nrows) ? A[(size_t)grow * HH + kc + ka] : 0.f;
            Ast[ka][r] = v;
        }
#pragma unroll
        for (int idx = tid; idx < KC * 128; idx += 256) {
            int kb = idx >> 7;
            int cb = idx & 127;
            Bs[kb][cb] = B[(size_t)(kc + kb) * ncols + col0 + cb];
        }
        __syncthreads();

#pragma unroll 8
        for (int k = 0; k < KC; k++) {
            float4 a  = *(const float4*)&Ast[k][ty * 4];
            float4 b0 = *(const float4*)&Bs[k][tx * 8];
            float4 b1 = *(const float4*)&Bs[k][tx * 8 + 4];
            float av[4] = {a.x, a.y, a.z, a.w};
            float bv[8] = {b0.x, b0.y, b0.z, b0.w, b1.x, b1.y, b1.z, b1.w};
#pragma unroll
            for (int i = 0; i < 4; i++)
#pragma unroll
                for (int j = 0; j < 8; j++) acc[i][j] += av[i] * bv[j];
        }
        __syncthreads();
    }

    float bvals[8];
#pragma unroll
    for (int j = 0; j < 8; j++) bvals[j] = bias ? bias[col0 + tx * 8 + j] : 0.f;

#pragma unroll
    for (int i = 0; i < 4; i++) {
        int grow = row0 + ty * 4 + i;
        if (grow < nrows) {
            float4 o0 = make_float4(acc[i][0] + bvals[0], acc[i][1] + bvals[1],
                                    acc[i][2] + bvals[2], acc[i][3] + bvals[3]);
            float4 o1 = make_float4(acc[i][4] + bvals[4], acc[i][5] + bvals[5],
                                    acc[i][6] + bvals[6], acc[i][7] + bvals[7]);
            float* crow = &C[(size_t)grow * ncols + col0 + tx * 8];
            *(float4*)(crow)     = o0;
            *(float4*)(crow + 4) = o1;
        }
    }
}

// ---------------- edge gather * weight -> vector red scatter-add ----------------
// one warp per edge; each lane handles one float4 (32 lanes * 4 = 128 features)
__global__ __launch_bounds__(256) void edge_scatter_kernel(
    const float* __restrict__ m, const float* __restrict__ ew,
    const void* __restrict__ ei, float* __restrict__ agg)
{
    long long gid = (long long)blockIdx.x * blockDim.x + threadIdx.x;
    int edge = (int)(gid >> 5);
    int lane = (int)(gid & 31);
    if (edge >= EE) return;

    int s, d;
    if (g_idx64) {
        const long long* e64 = (const long long*)ei;
        s = (int)e64[edge];
        d = (int)e64[EE + edge];
    } else {
        const int* e32 = (const int*)ei;
        s = e32[edge];
        d = e32[EE + edge];
    }
    // safety clamp: a bad index becomes a wrong answer (diagnosable), not an IMA
    if ((unsigned)s >= NN || (unsigned)d >= NN) return;

    float w = ew[edge];
    float4 v = *(const float4*)(m + (size_t)s * HH + lane * 4);
    v.x *= w; v.y *= w; v.z *= w; v.w *= w;

    float* dstp = agg + (size_t)d * HH + lane * 4;
    asm volatile("red.global.add.v4.f32 [%0], {%1, %2, %3, %4};"
                 :: "l"(dstp), "f"(v.x), "f"(v.y), "f"(v.z), "f"(v.w)
                 : "memory");
}

// ---------------- GRU elementwise ----------------
__global__ __launch_bounds__(256) void gru_elem_kernel(
    const float* __restrict__ gi, const float* __restrict__ gh,
    const float* __restrict__ x, float* __restrict__ xout, int n4)
{
    int idx = blockIdx.x * blockDim.x + threadIdx.x;
    if (idx >= n4) return;
    int node = idx >> 5;       // 32 float4 per node (H=128)
    int c4   = idx & 31;

    const float4* gi4 = (const float4*)gi;  // node stride 96 float4
    const float4* gh4 = (const float4*)gh;
    size_t base = (size_t)node * 96 + c4;

    float4 ir = gi4[base];
    float4 iz = gi4[base + 32];
    float4 in_ = gi4[base + 64];
    float4 hr = gh4[base];
    float4 hz = gh4[base + 32];
    float4 hn = gh4[base + 64];
    float4 xv = ((const float4*)x)[idx];

    float4 o;
    {
        float r  = 1.f / (1.f + __expf(-(ir.x + hr.x)));
        float zg = 1.f / (1.f + __expf(-(iz.x + hz.x)));
        float nn = tanhf(in_.x + r * hn.x);
        o.x = (1.f - zg) * nn + zg * xv.x;
    }
    {
        float r  = 1.f / (1.f + __expf(-(ir.y + hr.y)));
        float zg = 1.f / (1.f + __expf(-(iz.y + hz.y)));
        float nn = tanhf(in_.y + r * hn.y);
        o.y = (1.f - zg) * nn + zg * xv.y;
    }
    {
        float r  = 1.f / (1.f + __expf(-(ir.z + hr.z)));
        float zg = 1.f / (1.f + __expf(-(iz.z + hz.z)));
        float nn = tanhf(in_.z + r * hn.z);
        o.z = (1.f - zg) * nn + zg * xv.z;
    }
    {
        float r  = 1.f / (1.f + __expf(-(ir.w + hr.w)));
        float zg = 1.f / (1.f + __expf(-(iz.w + hz.w)));
        float nn = tanhf(in_.w + r * hn.w);
        o.w = (1.f - zg) * nn + zg * xv.w;
    }
    ((float4*)xout)[idx] = o;
}

// ---------------- host ----------------
extern "C" void kernel_launch(void* const* d_in, const int* in_sizes, int n_in,
                              void* d_out, int out_size)
{
    // Size-based identification with positional fallback.
    const float* z = nullptr; const float* ew = nullptr; const void* ei = nullptr;
    const float* mats[3] = {nullptr, nullptr, nullptr}; int nmat = 0;
    const float* vecs[2] = {nullptr, nullptr};          int nvec = 0;
    for (int i = 0; i < n_in; i++) {
        int sz = in_sizes[i];
        if      (sz == NN * HH)      z  = (const float*)d_in[i];
        else if (sz == EE)           ew = (const float*)d_in[i];
        else if (sz == 2 * EE)       ei = d_in[i];
        else if (sz == 3 * HH * HH) { if (nmat < 3) mats[nmat++] = (const float*)d_in[i]; }
        else if (sz == 3 * HH)      { if (nvec < 2) vecs[nvec++] = (const float*)d_in[i]; }
    }
    // positional fallback (metadata order: z, edge_weight, weight, w_ih, w_hh, b_ih, b_hh, edge_index)
    if (!z  && n_in > 0) z  = (const float*)d_in[0];
    if (!ew && n_in > 1) ew = (const float*)d_in[1];
    if (nmat < 3) { mats[0] = (const float*)d_in[2]; mats[1] = (const float*)d_in[3]; mats[2] = (const float*)d_in[4]; }
    if (nvec < 2) { vecs[0] = (const float*)d_in[5]; vecs[1] = (const float*)d_in[6]; }
    if (!ei && n_in > 7) ei = d_in[7];

    const float* weight = mats[0];
    const float* w_ih   = mats[1];
    const float* w_hh   = mats[2];
    const float* b_ih   = vecs[0];
    const float* b_hh   = vecs[1];
    float*       out    = (float*)d_out;

    float *pm, *pagg, *pgi, *pgh, *px, *pwih, *pwhh;
    cudaGetSymbolAddress((void**)&pm,   g_m);
    cudaGetSymbolAddress((void**)&pagg, g_agg);
    cudaGetSymbolAddress((void**)&pgi,  g_gi);
    cudaGetSymbolAddress((void**)&pgh,  g_gh);
    cudaGetSymbolAddress((void**)&px,   g_x);
    cudaGetSymbolAddress((void**)&pwih, g_wt_ih);
    cudaGetSymbolAddress((void**)&pwhh, g_wt_hh);

    const int GMX = (NN + BM - 1) / BM;               // 1563
    const int n4  = NN * (HH / 4);
    const int zgrid = (n4 + 255) / 256;
    const long long ethreads = (long long)EE * 32;
    const int egrid = (int)((ethreads + 255) / 256);  // 200000

    detect_idx_kernel<<<1, 256>>>((const int*)ei);
    transpose_w_kernel<<<(H3 * HH + 255) / 256, 256>>>(w_ih, pwih);
    transpose_w_kernel<<<(H3 * HH + 255) / 256, 256>>>(w_hh, pwhh);

    const float* x = z;
    for (int l = 0; l < LL; l++) {
        gemm_bias_kernel<<<dim3(GMX, 1), 256>>>(x, weight + (size_t)l * HH * HH,
                                                nullptr, pm, NN, HH);
        zero_kernel<<<zgrid, 256>>>((float4*)pagg, n4);
        edge_scatter_kernel<<<egrid, 256>>>(pm, ew, ei, pagg);
        gemm_bias_kernel<<<dim3(GMX, 3), 256>>>(pagg, pwih, b_ih, pgi, NN, H3);
        gemm_bias_kernel<<<dim3(GMX, 3), 256>>>(x,    pwhh, b_hh, pgh, NN, H3);
        float* xout = (l == LL - 1) ? out : px;
        gru_elem_kernel<<<zgrid, 256>>>(pgi, pgh, x, xout, n4);
        x = px;
    }
}

// round 9
// speedup vs baseline: 1.2146x; 1.2146x over previous
#include <cuda_runtime.h>
#include <cstdint>

#define NN 100000
#define EE 1600000
#define HH 128
#define H3 384
#define LL 3

// ---------------- scratch (static device globals; no allocation) ----------------
__device__ __align__(256) float g_m[(size_t)NN * HH];     // m = x @ W[l]
__device__ __align__(256) float g_agg[(size_t)NN * HH];   // scatter-add target
__device__ __align__(256) float g_gi[(size_t)NN * H3];    // agg @ w_ih^T + b_ih
__device__ __align__(256) float g_gh[(size_t)NN * H3];    // x   @ w_hh^T + b_hh
__device__ __align__(256) float g_x[(size_t)NN * HH];     // hidden state ping buffer
__device__ __align__(256) float g_wt_ih[(size_t)HH * H3]; // w_ih transposed -> [128][384]
__device__ __align__(256) float g_wt_hh[(size_t)HH * H3]; // w_hh transposed -> [128][384]
__device__ int g_idx64;                                    // 1 if edge_index buffer is int64

// ---------------- detect edge_index dtype ----------------
__global__ void detect_idx_kernel(const int* __restrict__ ei32) {
    int bad = 0;
    for (int i = threadIdx.x; i < 4096; i += blockDim.x) {
        if ((i & 1) && ei32[i] != 0) bad = 1;
    }
    bad = __syncthreads_or(bad);
    if (threadIdx.x == 0) g_idx64 = bad ? 0 : 1;
}

// ---------------- transpose [384][128] -> [128][384] ----------------
__global__ void transpose_w_kernel(const float* __restrict__ w, float* __restrict__ wt) {
    int i = blockIdx.x * blockDim.x + threadIdx.x;
    if (i < H3 * HH) {
        int j = i / HH;   // 0..383
        int k = i % HH;   // 0..127
        wt[k * H3 + j] = w[i];
    }
}

// ---------------- zero buffer (float4) ----------------
__global__ void zero_kernel(float4* __restrict__ p, int n4) {
    int i = blockIdx.x * blockDim.x + threadIdx.x;
    if (i < n4) p[i] = make_float4(0.f, 0.f, 0.f, 0.f);
}

// ---------------- fp32 GEMM: C[nrows x ncols] = A[nrows x 128] @ B[128 x ncols] (+bias) ----
// 128x128 tile, 256 threads, 8x8 per thread, BK=16, double-buffered smem,
// register-prefetch pipeline. K is fixed at HH=128.
#define BM 128
#define BN 128
#define BK 16
#define ASTRIDE (BM + 4)   // 132 floats; 132*4B = 528B, multiple of 16 -> float4-safe

__global__ __launch_bounds__(256, 2) void gemm_bias_kernel(
    const float* __restrict__ A, const float* __restrict__ B,
    const float* __restrict__ bias, float* __restrict__ C,
    int nrows, int ncols)
{
    __shared__ __align__(16) float As[2][BK][ASTRIDE];
    __shared__ __align__(16) float Bs[2][BK][BN];

    const int tid = threadIdx.x;
    const int tx  = tid & 15;            // cols tx*8 .. tx*8+7
    const int ty  = tid >> 4;            // rows ty*8 .. ty*8+7
    const int row0 = blockIdx.x * BM;
    const int col0 = blockIdx.y * BN;

    // A-tile load mapping: thread covers rows (tid>>2) and (tid>>2)+64, k = (tid&3)*4 .. +3
    const int arow = tid >> 2;           // 0..63
    const int ak   = (tid & 3) * 4;      // 0,4,8,12
    // B-tile load mapping: thread covers k rows (tid>>5) and (tid>>5)+8, cols (tid&31)*4 .. +3
    const int bk   = tid >> 5;           // 0..7
    const int bcol = (tid & 31) * 4;

    float4 pa0, pa1, pb0, pb1;

    // prologue: load stage for kc=0
    {
        int r0 = row0 + arow, r1 = row0 + arow + 64;
        pa0 = (r0 < nrows) ? *(const float4*)&A[(size_t)r0 * HH + 0 + ak] : make_float4(0.f,0.f,0.f,0.f);
        pa1 = (r1 < nrows) ? *(const float4*)&A[(size_t)r1 * HH + 0 + ak] : make_float4(0.f,0.f,0.f,0.f);
        pb0 = *(const float4*)&B[(size_t)(0 + bk) * ncols + col0 + bcol];
        pb1 = *(const float4*)&B[(size_t)(0 + bk + 8) * ncols + col0 + bcol];
        As[0][ak+0][arow]    = pa0.x; As[0][ak+1][arow]    = pa0.y;
        As[0][ak+2][arow]    = pa0.z; As[0][ak+3][arow]    = pa0.w;
        As[0][ak+0][arow+64] = pa1.x; As[0][ak+1][arow+64] = pa1.y;
        As[0][ak+2][arow+64] = pa1.z; As[0][ak+3][arow+64] = pa1.w;
        *(float4*)&Bs[0][bk][bcol]     = pb0;
        *(float4*)&Bs[0][bk+8][bcol]   = pb1;
    }
    __syncthreads();

    float acc[8][8];
#pragma unroll
    for (int i = 0; i < 8; i++)
#pragma unroll
        for (int j = 0; j < 8; j++) acc[i][j] = 0.f;

    int cur = 0;
#pragma unroll
    for (int kc = 0; kc < HH; kc += BK) {
        const bool has_next = (kc + BK < HH);
        if (has_next) {
            int kn = kc + BK;
            int r0 = row0 + arow, r1 = row0 + arow + 64;
            pa0 = (r0 < nrows) ? *(const float4*)&A[(size_t)r0 * HH + kn + ak] : make_float4(0.f,0.f,0.f,0.f);
            pa1 = (r1 < nrows) ? *(const float4*)&A[(size_t)r1 * HH + kn + ak] : make_float4(0.f,0.f,0.f,0.f);
            pb0 = *(const float4*)&B[(size_t)(kn + bk) * ncols + col0 + bcol];
            pb1 = *(const float4*)&B[(size_t)(kn + bk + 8) * ncols + col0 + bcol];
        }

#pragma unroll
        for (int k = 0; k < BK; k++) {
            float4 a0 = *(const float4*)&As[cur][k][ty * 8];
            float4 a1 = *(const float4*)&As[cur][k][ty * 8 + 4];
            float4 b0 = *(const float4*)&Bs[cur][k][tx * 8];
            float4 b1 = *(const float4*)&Bs[cur][k][tx * 8 + 4];
            float av[8] = {a0.x, a0.y, a0.z, a0.w, a1.x, a1.y, a1.z, a1.w};
            float bv[8] = {b0.x, b0.y, b0.z, b0.w, b1.x, b1.y, b1.z, b1.w};
#pragma unroll
            for (int i = 0; i < 8; i++)
#pragma unroll
                for (int j = 0; j < 8; j++) acc[i][j] += av[i] * bv[j];
        }

        if (has_next) {
            int nxt = cur ^ 1;
            As[nxt][ak+0][arow]    = pa0.x; As[nxt][ak+1][arow]    = pa0.y;
            As[nxt][ak+2][arow]    = pa0.z; As[nxt][ak+3][arow]    = pa0.w;
            As[nxt][ak+0][arow+64] = pa1.x; As[nxt][ak+1][arow+64] = pa1.y;
            As[nxt][ak+2][arow+64] = pa1.z; As[nxt][ak+3][arow+64] = pa1.w;
            *(float4*)&Bs[nxt][bk][bcol]   = pb0;
            *(float4*)&Bs[nxt][bk+8][bcol] = pb1;
            __syncthreads();
            cur = nxt;
        }
    }

    float bvals[8];
#pragma unroll
    for (int j = 0; j < 8; j++) bvals[j] = bias ? bias[col0 + tx * 8 + j] : 0.f;

#pragma unroll
    for (int i = 0; i < 8; i++) {
        int grow = row0 + ty * 8 + i;
        if (grow < nrows) {
            float4 o0 = make_float4(acc[i][0] + bvals[0], acc[i][1] + bvals[1],
                                    acc[i][2] + bvals[2], acc[i][3] + bvals[3]);
            float4 o1 = make_float4(acc[i][4] + bvals[4], acc[i][5] + bvals[5],
                                    acc[i][6] + bvals[6], acc[i][7] + bvals[7]);
            float* crow = &C[(size_t)grow * ncols + col0 + tx * 8];
            *(float4*)(crow)     = o0;
            *(float4*)(crow + 4) = o1;
        }
    }
}

// ---------------- edge gather * weight -> vector red scatter-add ----------------
__global__ __launch_bounds__(256) void edge_scatter_kernel(
    const float* __restrict__ m, const float* __restrict__ ew,
    const void* __restrict__ ei, float* __restrict__ agg)
{
    long long gid = (long long)blockIdx.x * blockDim.x + threadIdx.x;
    int edge = (int)(gid >> 5);
    int lane = (int)(gid & 31);
    if (edge >= EE) return;

    int s, d;
    if (g_idx64) {
        const long long* e64 = (const long long*)ei;
        s = (int)e64[edge];
        d = (int)e64[EE + edge];
    } else {
        const int* e32 = (const int*)ei;
        s = e32[edge];
        d = e32[EE + edge];
    }
    if ((unsigned)s >= NN || (unsigned)d >= NN) return;

    float w = ew[edge];
    float4 v = *(const float4*)(m + (size_t)s * HH + lane * 4);
    v.x *= w; v.y *= w; v.z *= w; v.w *= w;

    float* dstp = agg + (size_t)d * HH + lane * 4;
    asm volatile("red.global.add.v4.f32 [%0], {%1, %2, %3, %4};"
                 :: "l"(dstp), "f"(v.x), "f"(v.y), "f"(v.z), "f"(v.w)
                 : "memory");
}

// ---------------- GRU elementwise ----------------
__global__ __launch_bounds__(256) void gru_elem_kernel(
    const float* __restrict__ gi, const float* __restrict__ gh,
    const float* __restrict__ x, float* __restrict__ xout, int n4)
{
    int idx = blockIdx.x * blockDim.x + threadIdx.x;
    if (idx >= n4) return;
    int node = idx >> 5;       // 32 float4 per node (H=128)
    int c4   = idx & 31;

    const float4* gi4 = (const float4*)gi;  // node stride 96 float4
    const float4* gh4 = (const float4*)gh;
    size_t base = (size_t)node * 96 + c4;

    float4 ir = gi4[base];
    float4 iz = gi4[base + 32];
    float4 in_ = gi4[base + 64];
    float4 hr = gh4[base];
    float4 hz = gh4[base + 32];
    float4 hn = gh4[base + 64];
    float4 xv = ((const float4*)x)[idx];

    float4 o;
    {
        float r  = 1.f / (1.f + __expf(-(ir.x + hr.x)));
        float zg = 1.f / (1.f + __expf(-(iz.x + hz.x)));
        float nn = tanhf(in_.x + r * hn.x);
        o.x = (1.f - zg) * nn + zg * xv.x;
    }
    {
        float r  = 1.f / (1.f + __expf(-(ir.y + hr.y)));
        float zg = 1.f / (1.f + __expf(-(iz.y + hz.y)));
        float nn = tanhf(in_.y + r * hn.y);
        o.y = (1.f - zg) * nn + zg * xv.y;
    }
    {
        float r  = 1.f / (1.f + __expf(-(ir.z + hr.z)));
        float zg = 1.f / (1.f + __expf(-(iz.z + hz.z)));
        float nn = tanhf(in_.z + r * hn.z);
        o.z = (1.f - zg) * nn + zg * xv.z;
    }
    {
        float r  = 1.f / (1.f + __expf(-(ir.w + hr.w)));
        float zg = 1.f / (1.f + __expf(-(iz.w + hz.w)));
        float nn = tanhf(in_.w + r * hn.w);
        o.w = (1.f - zg) * nn + zg * xv.w;
    }
    ((float4*)xout)[idx] = o;
}

// ---------------- host ----------------
extern "C" void kernel_launch(void* const* d_in, const int* in_sizes, int n_in,
                              void* d_out, int out_size)
{
    const float* z = nullptr; const float* ew = nullptr; const void* ei = nullptr;
    const float* mats[3] = {nullptr, nullptr, nullptr}; int nmat = 0;
    const float* vecs[2] = {nullptr, nullptr};          int nvec = 0;
    for (int i = 0; i < n_in; i++) {
        int sz = in_sizes[i];
        if      (sz == NN * HH)      z  = (const float*)d_in[i];
        else if (sz == EE)           ew = (const float*)d_in[i];
        else if (sz == 2 * EE)       ei = d_in[i];
        else if (sz == 3 * HH * HH) { if (nmat < 3) mats[nmat++] = (const float*)d_in[i]; }
        else if (sz == 3 * HH)      { if (nvec < 2) vecs[nvec++] = (const float*)d_in[i]; }
    }
    if (!z  && n_in > 0) z  = (const float*)d_in[0];
    if (!ew && n_in > 1) ew = (const float*)d_in[1];
    if (nmat < 3) { mats[0] = (const float*)d_in[2]; mats[1] = (const float*)d_in[3]; mats[2] = (const float*)d_in[4]; }
    if (nvec < 2) { vecs[0] = (const float*)d_in[5]; vecs[1] = (const float*)d_in[6]; }
    if (!ei && n_in > 7) ei = d_in[7];

    const float* weight = mats[0];
    const float* w_ih   = mats[1];
    const float* w_hh   = mats[2];
    const float* b_ih   = vecs[0];
    const float* b_hh   = vecs[1];
    float*       out    = (float*)d_out;

    float *pm, *pagg, *pgi, *pgh, *px, *pwih, *pwhh;
    cudaGetSymbolAddress((void**)&pm,   g_m);
    cudaGetSymbolAddress((void**)&pagg, g_agg);
    cudaGetSymbolAddress((void**)&pgi,  g_gi);
    cudaGetSymbolAddress((void**)&pgh,  g_gh);
    cudaGetSymbolAddress((void**)&px,   g_x);
    cudaGetSymbolAddress((void**)&pwih, g_wt_ih);
    cudaGetSymbolAddress((void**)&pwhh, g_wt_hh);

    const int GMX = (NN + BM - 1) / BM;               // 782
    const int n4  = NN * (HH / 4);
    const int zgrid = (n4 + 255) / 256;
    const long long ethreads = (long long)EE * 32;
    const int egrid = (int)((ethreads + 255) / 256);  // 200000

    detect_idx_kernel<<<1, 256>>>((const int*)ei);
    transpose_w_kernel<<<(H3 * HH + 255) / 256, 256>>>(w_ih, pwih);
    transpose_w_kernel<<<(H3 * HH + 255) / 256, 256>>>(w_hh, pwhh);

    const float* x = z;
    for (int l = 0; l < LL; l++) {
        gemm_bias_kernel<<<dim3(GMX, 1), 256>>>(x, weight + (size_t)l * HH * HH,
                                                nullptr, pm, NN, HH);
        zero_kernel<<<zgrid, 256>>>((float4*)pagg, n4);
        edge_scatter_kernel<<<egrid, 256>>>(pm, ew, ei, pagg);
        gemm_bias_kernel<<<dim3(GMX, 3), 256>>>(pagg, pwih, b_ih, pgi, NN, H3);
        gemm_bias_kernel<<<dim3(GMX, 3), 256>>>(x,    pwhh, b_hh, pgh, NN, H3);
        float* xout = (l == LL - 1) ? out : px;
        gru_elem_kernel<<<zgrid, 256>>>(pgi, pgh, x, xout, n4);
        x = px;
    }
}

// round 10
// speedup vs baseline: 1.7735x; 1.4601x over previous
#include <cuda_runtime.h>
#include <cstdint>

#define NN 100000
#define EE 1600000
#define HH 128
#define H3 384
#define LL 3

// ---------------- scratch (static device globals; no allocation) ----------------
__device__ __align__(256) float g_m[(size_t)NN * HH];     // m = x @ W[l]
__device__ __align__(256) float g_agg[(size_t)NN * HH];   // scatter-add target
__device__ __align__(256) float g_gi[(size_t)NN * H3];    // agg @ w_ih^T + b_ih
__device__ __align__(256) float g_gh[(size_t)NN * H3];    // x   @ w_hh^T + b_hh
__device__ __align__(256) float g_x[(size_t)NN * HH];     // hidden state ping buffer
__device__ int g_idx64;

// bf16 hi/lo split weights, all stored [n][k] (k contiguous, K=128)
__device__ __align__(256) unsigned short g_B1hi[3 * HH * HH];   // weight[l] transposed
__device__ __align__(256) unsigned short g_B1lo[3 * HH * HH];
__device__ __align__(256) unsigned short g_Bihhi[H3 * HH];      // w_ih natural layout
__device__ __align__(256) unsigned short g_Bihlo[H3 * HH];
__device__ __align__(256) unsigned short g_Bhhhi[H3 * HH];
__device__ __align__(256) unsigned short g_Bhhlo[H3 * HH];

// ---------------- bf16 split helpers ----------------
__device__ __forceinline__ unsigned bf16h(float f) {
    unsigned x = __float_as_uint(f);
    return (x + 0x7fffu + ((x >> 16) & 1u)) >> 16;   // rn-even to bf16 bits
}
__device__ __forceinline__ float bf16f(unsigned b) { return __uint_as_float(b << 16); }

// ---------------- detect edge_index dtype ----------------
__global__ void detect_idx_kernel(const int* __restrict__ ei32) {
    int bad = 0;
    for (int i = threadIdx.x; i < 4096; i += blockDim.x)
        if ((i & 1) && ei32[i] != 0) bad = 1;
    bad = __syncthreads_or(bad);
    if (threadIdx.x == 0) g_idx64 = bad ? 0 : 1;
}

// ---------------- split weight[l] (k-major [k][n]) -> transposed [n][k] hi/lo ----------------
__global__ void split_w1_kernel(const float* __restrict__ w,
                                unsigned short* __restrict__ hi,
                                unsigned short* __restrict__ lo) {
    int i = blockIdx.x * blockDim.x + threadIdx.x;
    if (i >= 3 * HH * HH) return;
    int l = i >> 14, rem = i & 16383;
    int k = rem >> 7, n = rem & 127;
    float f = w[i];
    unsigned h = bf16h(f);
    unsigned lbits = bf16h(f - bf16f(h));
    int o = l * HH * HH + n * HH + k;
    hi[o] = (unsigned short)h;
    lo[o] = (unsigned short)lbits;
}

// ---------------- elementwise split (natural [n][k] layout) ----------------
__global__ void split_w_kernel(const float* __restrict__ w, int count,
                               unsigned short* __restrict__ hi,
                               unsigned short* __restrict__ lo) {
    int i = blockIdx.x * blockDim.x + threadIdx.x;
    if (i >= count) return;
    float f = w[i];
    unsigned h = bf16h(f);
    hi[i] = (unsigned short)h;
    lo[i] = (unsigned short)bf16h(f - bf16f(h));
}

// ---------------- zero buffer (float4) ----------------
__global__ void zero_kernel(float4* __restrict__ p, int n4) {
    int i = blockIdx.x * blockDim.x + threadIdx.x;
    if (i < n4) p[i] = make_float4(0.f, 0.f, 0.f, 0.f);
}

// ---------------- tensor-core GEMM: C[nrows x ncols] = A[nrows x 128] @ B + bias ----------------
// B given pre-split as bf16 hi/lo in [n][k] layout (k contiguous, K=128).
// Computes in bf16 3-term split: hi*hi + hi*lo + lo*hi  (fp32 mma accumulators).
// Block: 256 threads = 8 warps (4M x 2N). Block tile 128x64, warp tile 32x32, BK=32.
#define GBM 128
#define GBN 64
#define GBK 32
#define AST 20   // smem row stride in u32 words (16 data + 4 pad): conflict-free frag loads

__device__ __forceinline__ void mma_bf16(float* c, const unsigned* a, unsigned b0, unsigned b1) {
    asm volatile(
        "mma.sync.aligned.m16n8k16.row.col.f32.bf16.bf16.f32 "
        "{%0,%1,%2,%3}, {%4,%5,%6,%7}, {%8,%9}, {%0,%1,%2,%3};"
        : "+f"(c[0]), "+f"(c[1]), "+f"(c[2]), "+f"(c[3])
        : "r"(a[0]), "r"(a[1]), "r"(a[2]), "r"(a[3]), "r"(b0), "r"(b1));
}

__global__ __launch_bounds__(256, 2) void mma_gemm_kernel(
    const float* __restrict__ A,
    const unsigned short* __restrict__ Bhi16, const unsigned short* __restrict__ Blo16,
    const float* __restrict__ bias, float* __restrict__ C,
    int nrows, int ncols)
{
    __shared__ __align__(16) unsigned sAhi[GBM * AST];
    __shared__ __align__(16) unsigned sAlo[GBM * AST];
    __shared__ __align__(16) unsigned sBhi[GBN * AST];
    __shared__ __align__(16) unsigned sBlo[GBN * AST];

    const int tid  = threadIdx.x;
    const int lane = tid & 31;
    const int wid  = tid >> 5;
    const int g    = lane >> 2;     // 0..7
    const int t    = lane & 3;      // 0..3
    const int wm   = (wid & 3) * 32;
    const int wn   = (wid >> 2) * 32;
    const int row0 = blockIdx.x * GBM;
    const int col0 = blockIdx.y * GBN;

    const unsigned* Bhi = (const unsigned*)Bhi16;  // [n][64 words]
    const unsigned* Blo = (const unsigned*)Blo16;

    // staging maps
    const int ar = tid >> 1;             // A row 0..127
    const int akh = (tid & 1) * 16;      // k offset 0/16
    const int bn = tid >> 2;             // B n 0..63
    const int bkw = (tid & 3) * 4;       // word offset in chunk

    float acc[2][4][4];
#pragma unroll
    for (int i = 0; i < 2; i++)
#pragma unroll
        for (int j = 0; j < 4; j++)
#pragma unroll
            for (int q = 0; q < 4; q++) acc[i][j][q] = 0.f;

#pragma unroll
    for (int kc = 0; kc < HH; kc += GBK) {
        // ---- stage A (fp32 -> bf16 hi/lo) ----
        {
            int grow = row0 + ar;
            float v[16];
            if (grow < nrows) {
                const float* ap = A + (size_t)grow * HH + kc + akh;
#pragma unroll
                for (int q = 0; q < 4; q++) {
                    float4 f = *(const float4*)(ap + q * 4);
                    v[q*4+0] = f.x; v[q*4+1] = f.y; v[q*4+2] = f.z; v[q*4+3] = f.w;
                }
            } else {
#pragma unroll
                for (int q = 0; q < 16; q++) v[q] = 0.f;
            }
            int base = ar * AST + (akh >> 1);
#pragma unroll
            for (int j = 0; j < 8; j++) {
                float f0 = v[2*j], f1 = v[2*j+1];
                unsigned h0 = bf16h(f0), h1 = bf16h(f1);
                unsigned l0 = bf16h(f0 - bf16f(h0)), l1 = bf16h(f1 - bf16f(h1));
                sAhi[base + j] = h0 | (h1 << 16);
                sAlo[base + j] = l0 | (l1 << 16);
            }
        }
        // ---- stage B (bf16, direct) ----
        {
            int gbase = (col0 + bn) * (HH / 2) + (kc >> 1) + bkw;
            uint4 h = *(const uint4*)(Bhi + gbase);
            uint4 l = *(const uint4*)(Blo + gbase);
            int sb = bn * AST + bkw;
            sBhi[sb+0] = h.x; sBhi[sb+1] = h.y; sBhi[sb+2] = h.z; sBhi[sb+3] = h.w;
            sBlo[sb+0] = l.x; sBlo[sb+1] = l.y; sBlo[sb+2] = l.z; sBlo[sb+3] = l.w;
        }
        __syncthreads();

        // ---- compute: 2 k16 steps ----
#pragma unroll
        for (int s = 0; s < 2; s++) {
            unsigned ahi[2][4], alo[2][4];
#pragma unroll
            for (int ma = 0; ma < 2; ma++) {
                int b0 = (wm + ma * 16 + g) * AST + s * 8 + t;
                int b1 = (wm + ma * 16 + 8 + g) * AST + s * 8 + t;
                ahi[ma][0] = sAhi[b0];     ahi[ma][1] = sAhi[b1];
                ahi[ma][2] = sAhi[b0 + 4]; ahi[ma][3] = sAhi[b1 + 4];
                alo[ma][0] = sAlo[b0];     alo[ma][1] = sAlo[b1];
                alo[ma][2] = sAlo[b0 + 4]; alo[ma][3] = sAlo[b1 + 4];
            }
#pragma unroll
            for (int na = 0; na < 4; na++) {
                int bb = (wn + na * 8 + g) * AST + s * 8 + t;
                unsigned bh0 = sBhi[bb], bh1 = sBhi[bb + 4];
                unsigned bl0 = sBlo[bb], bl1 = sBlo[bb + 4];
#pragma unroll
                for (int ma = 0; ma < 2; ma++) {
                    mma_bf16(acc[ma][na], ahi[ma], bh0, bh1);
                    mma_bf16(acc[ma][na], ahi[ma], bl0, bl1);
                    mma_bf16(acc[ma][na], alo[ma], bh0, bh1);
                }
            }
        }
        __syncthreads();
    }

    // ---- epilogue ----
#pragma unroll
    for (int ma = 0; ma < 2; ma++) {
#pragma unroll
        for (int na = 0; na < 4; na++) {
            int col = col0 + wn + na * 8 + t * 2;
            float b0 = bias ? bias[col] : 0.f;
            float b1 = bias ? bias[col + 1] : 0.f;
            int r0 = row0 + wm + ma * 16 + g;
            if (r0 < nrows) {
                float2 o = make_float2(acc[ma][na][0] + b0, acc[ma][na][1] + b1);
                *(float2*)&C[(size_t)r0 * ncols + col] = o;
            }
            int r1 = r0 + 8;
            if (r1 < nrows) {
                float2 o = make_float2(acc[ma][na][2] + b0, acc[ma][na][3] + b1);
                *(float2*)&C[(size_t)r1 * ncols + col] = o;
            }
        }
    }
}

// ---------------- edge gather * weight -> vector red scatter-add ----------------
__global__ __launch_bounds__(256) void edge_scatter_kernel(
    const float* __restrict__ m, const float* __restrict__ ew,
    const void* __restrict__ ei, float* __restrict__ agg)
{
    long long gid = (long long)blockIdx.x * blockDim.x + threadIdx.x;
    int edge = (int)(gid >> 5);
    int lane = (int)(gid & 31);
    if (edge >= EE) return;

    int s, d;
    if (g_idx64) {
        const long long* e64 = (const long long*)ei;
        s = (int)e64[edge];
        d = (int)e64[EE + edge];
    } else {
        const int* e32 = (const int*)ei;
        s = e32[edge];
        d = e32[EE + edge];
    }
    if ((unsigned)s >= NN || (unsigned)d >= NN) return;

    float w = ew[edge];
    float4 v = *(const float4*)(m + (size_t)s * HH + lane * 4);
    v.x *= w; v.y *= w; v.z *= w; v.w *= w;

    float* dstp = agg + (size_t)d * HH + lane * 4;
    asm volatile("red.global.add.v4.f32 [%0], {%1, %2, %3, %4};"
                 :: "l"(dstp), "f"(v.x), "f"(v.y), "f"(v.z), "f"(v.w)
                 : "memory");
}

// ---------------- GRU elementwise ----------------
__global__ __launch_bounds__(256) void gru_elem_kernel(
    const float* __restrict__ gi, const float* __restrict__ gh,
    const float* __restrict__ x, float* __restrict__ xout, int n4)
{
    int idx = blockIdx.x * blockDim.x + threadIdx.x;
    if (idx >= n4) return;
    int node = idx >> 5;
    int c4   = idx & 31;

    const float4* gi4 = (const float4*)gi;
    const float4* gh4 = (const float4*)gh;
    size_t base = (size_t)node * 96 + c4;

    float4 ir = gi4[base];
    float4 iz = gi4[base + 32];
    float4 in_ = gi4[base + 64];
    float4 hr = gh4[base];
    float4 hz = gh4[base + 32];
    float4 hn = gh4[base + 64];
    float4 xv = ((const float4*)x)[idx];

    float4 o;
    {
        float r  = 1.f / (1.f + __expf(-(ir.x + hr.x)));
        float zg = 1.f / (1.f + __expf(-(iz.x + hz.x)));
        float nn = tanhf(in_.x + r * hn.x);
        o.x = (1.f - zg) * nn + zg * xv.x;
    }
    {
        float r  = 1.f / (1.f + __expf(-(ir.y + hr.y)));
        float zg = 1.f / (1.f + __expf(-(iz.y + hz.y)));
        float nn = tanhf(in_.y + r * hn.y);
        o.y = (1.f - zg) * nn + zg * xv.y;
    }
    {
        float r  = 1.f / (1.f + __expf(-(ir.z + hr.z)));
        float zg = 1.f / (1.f + __expf(-(iz.z + hz.z)));
        float nn = tanhf(in_.z + r * hn.z);
        o.z = (1.f - zg) * nn + zg * xv.z;
    }
    {
        float r  = 1.f / (1.f + __expf(-(ir.w + hr.w)));
        float zg = 1.f / (1.f + __expf(-(iz.w + hz.w)));
        float nn = tanhf(in_.w + r * hn.w);
        o.w = (1.f - zg) * nn + zg * xv.w;
    }
    ((float4*)xout)[idx] = o;
}

// ---------------- host ----------------
extern "C" void kernel_launch(void* const* d_in, const int* in_sizes, int n_in,
                              void* d_out, int out_size)
{
    const float* z = nullptr; const float* ew = nullptr; const void* ei = nullptr;
    const float* mats[3] = {nullptr, nullptr, nullptr}; int nmat = 0;
    const float* vecs[2] = {nullptr, nullptr};          int nvec = 0;
    for (int i = 0; i < n_in; i++) {
        int sz = in_sizes[i];
        if      (sz == NN * HH)      z  = (const float*)d_in[i];
        else if (sz == EE)           ew = (const float*)d_in[i];
        else if (sz == 2 * EE)       ei = d_in[i];
        else if (sz == 3 * HH * HH) { if (nmat < 3) mats[nmat++] = (const float*)d_in[i]; }
        else if (sz == 3 * HH)      { if (nvec < 2) vecs[nvec++] = (const float*)d_in[i]; }
    }
    if (!z  && n_in > 0) z  = (const float*)d_in[0];
    if (!ew && n_in > 1) ew = (const float*)d_in[1];
    if (nmat < 3) { mats[0] = (const float*)d_in[2]; mats[1] = (const float*)d_in[3]; mats[2] = (const float*)d_in[4]; }
    if (nvec < 2) { vecs[0] = (const float*)d_in[5]; vecs[1] = (const float*)d_in[6]; }
    if (!ei && n_in > 7) ei = d_in[7];

    const float* weight = mats[0];
    const float* w_ih   = mats[1];
    const float* w_hh   = mats[2];
    const float* b_ih   = vecs[0];
    const float* b_hh   = vecs[1];
    float*       out    = (float*)d_out;

    float *pm, *pagg, *pgi, *pgh, *px;
    unsigned short *pB1h, *pB1l, *pIhh, *pIhl, *pHhh, *pHhl;
    cudaGetSymbolAddress((void**)&pm,   g_m);
    cudaGetSymbolAddress((void**)&pagg, g_agg);
    cudaGetSymbolAddress((void**)&pgi,  g_gi);
    cudaGetSymbolAddress((void**)&pgh,  g_gh);
    cudaGetSymbolAddress((void**)&px,   g_x);
    cudaGetSymbolAddress((void**)&pB1h, g_B1hi);
    cudaGetSymbolAddress((void**)&pB1l, g_B1lo);
    cudaGetSymbolAddress((void**)&pIhh, g_Bihhi);
    cudaGetSymbolAddress((void**)&pIhl, g_Bihlo);
    cudaGetSymbolAddress((void**)&pHhh, g_Bhhhi);
    cudaGetSymbolAddress((void**)&pHhl, g_Bhhlo);

    const int GMX = (NN + GBM - 1) / GBM;             // 782
    const int n4  = NN * (HH / 4);
    const int zgrid = (n4 + 255) / 256;
    const long long ethreads = (long long)EE * 32;
    const int egrid = (int)((ethreads + 255) / 256);

    detect_idx_kernel<<<1, 256>>>((const int*)ei);
    split_w1_kernel<<<(3 * HH * HH + 255) / 256, 256>>>(weight, pB1h, pB1l);
    split_w_kernel<<<(H3 * HH + 255) / 256, 256>>>(w_ih, H3 * HH, pIhh, pIhl);
    split_w_kernel<<<(H3 * HH + 255) / 256, 256>>>(w_hh, H3 * HH, pHhh, pHhl);

    const float* x = z;
    for (int l = 0; l < LL; l++) {
        mma_gemm_kernel<<<dim3(GMX, HH / GBN), 256>>>(
            x, pB1h + (size_t)l * HH * HH, pB1l + (size_t)l * HH * HH,
            nullptr, pm, NN, HH);
        zero_kernel<<<zgrid, 256>>>((float4*)pagg, n4);
        edge_scatter_kernel<<<egrid, 256>>>(pm, ew, ei, pagg);
        mma_gemm_kernel<<<dim3(GMX, H3 / GBN), 256>>>(pagg, pIhh, pIhl, b_ih, pgi, NN, H3);
        mma_gemm_kernel<<<dim3(GMX, H3 / GBN), 256>>>(x,    pHhh, pHhl, b_hh, pgh, NN, H3);
        float* xout = (l == LL - 1) ? out : px;
        gru_elem_kernel<<<zgrid, 256>>>(pgi, pgh, x, xout, n4);
        x = px;
    }
}

// round 12
// speedup vs baseline: 1.8361x; 1.0353x over previous
#include <cuda_runtime.h>
#include <cstdint>

#define NN 100000
#define EE 1600000
#define HH 128
#define H3 384
#define LL 3

// ---------------- scratch (static device globals; no allocation) ----------------
__device__ __align__(256) float g_m[(size_t)NN * HH];     // m = x @ W[l]
__device__ __align__(256) float g_agg[(size_t)NN * HH];   // scatter-add target
__device__ __align__(256) float g_gi[(size_t)NN * H3];    // agg @ w_ih^T + b_ih
__device__ __align__(256) float g_gh[(size_t)NN * H3];    // x   @ w_hh^T + b_hh
__device__ __align__(256) float g_x[(size_t)NN * HH];     // hidden state ping buffer
__device__ int g_idx64;
__device__ __align__(256) int g_src[EE];
__device__ __align__(256) int g_dst[EE];

// bf16 hi/lo split weights, stored [n][k] (k contiguous, K=128)
__device__ __align__(256) unsigned short g_B1hi[3 * HH * HH];
__device__ __align__(256) unsigned short g_B1lo[3 * HH * HH];
__device__ __align__(256) unsigned short g_Bihhi[H3 * HH];
__device__ __align__(256) unsigned short g_Bihlo[H3 * HH];
__device__ __align__(256) unsigned short g_Bhhhi[H3 * HH];
__device__ __align__(256) unsigned short g_Bhhlo[H3 * HH];
// bf16 hi/lo split activations [n][k]
__device__ __align__(256) unsigned short g_xhi[(size_t)NN * HH];
__device__ __align__(256) unsigned short g_xlo[(size_t)NN * HH];
__device__ __align__(256) unsigned short g_ahi[(size_t)NN * HH];
__device__ __align__(256) unsigned short g_alo[(size_t)NN * HH];

// ---------------- bf16 split helpers ----------------
__device__ __forceinline__ unsigned bf16h(float f) {
    unsigned x = __float_as_uint(f);
    return (x + 0x7fffu + ((x >> 16) & 1u)) >> 16;   // rn-even to bf16 bits
}
__device__ __forceinline__ float bf16f(unsigned b) { return __uint_as_float(b << 16); }

// ---------------- detect edge_index dtype ----------------
__global__ void detect_idx_kernel(const int* __restrict__ ei32) {
    int bad = 0;
    for (int i = threadIdx.x; i < 4096; i += blockDim.x)
        if ((i & 1) && ei32[i] != 0) bad = 1;
    bad = __syncthreads_or(bad);
    if (threadIdx.x == 0) g_idx64 = bad ? 0 : 1;
}

// ---------------- decode edge_index -> int32 src/dst ----------------
__global__ __launch_bounds__(256) void prep_idx_kernel(const void* __restrict__ ei,
                                                       int* __restrict__ src,
                                                       int* __restrict__ dst) {
    int e = blockIdx.x * blockDim.x + threadIdx.x;
    if (e >= EE) return;
    int s, d;
    if (g_idx64) {
        const long long* p = (const long long*)ei;
        s = (int)p[e]; d = (int)p[EE + e];
    } else {
        const int* p = (const int*)ei;
        s = p[e]; d = p[EE + e];
    }
    if ((unsigned)s >= NN) s = 0;
    if ((unsigned)d >= NN) d = 0;
    src[e] = s; dst[e] = d;
}

// ---------------- split weight[l] ([k][n]) -> transposed [n][k] hi/lo ----------------
__global__ void split_w1_kernel(const float* __restrict__ w,
                                unsigned short* __restrict__ hi,
                                unsigned short* __restrict__ lo) {
    int i = blockIdx.x * blockDim.x + threadIdx.x;
    if (i >= 3 * HH * HH) return;
    int l = i >> 14, rem = i & 16383;
    int k = rem >> 7, n = rem & 127;
    float f = w[i];
    unsigned h = bf16h(f);
    unsigned lb = bf16h(f - bf16f(h));
    int o = l * HH * HH + n * HH + k;
    hi[o] = (unsigned short)h;
    lo[o] = (unsigned short)lb;
}

// ---------------- elementwise split ([n][k] natural) ----------------
__global__ void split_w_kernel(const float* __restrict__ w, int count,
                               unsigned short* __restrict__ hi,
                               unsigned short* __restrict__ lo) {
    int i = blockIdx.x * blockDim.x + threadIdx.x;
    if (i >= count) return;
    float f = w[i];
    unsigned h = bf16h(f);
    hi[i] = (unsigned short)h;
    lo[i] = (unsigned short)bf16h(f - bf16f(h));
}

// ---------------- split activations, vectorized x4 ----------------
__global__ __launch_bounds__(256) void split_act_kernel(
    const float4* __restrict__ a, int n4,
    uint2* __restrict__ hi, uint2* __restrict__ lo)
{
    int i = blockIdx.x * blockDim.x + threadIdx.x;
    if (i >= n4) return;
    float4 v = a[i];
    unsigned h0 = bf16h(v.x), h1 = bf16h(v.y), h2 = bf16h(v.z), h3 = bf16h(v.w);
    unsigned l0 = bf16h(v.x - bf16f(h0)), l1 = bf16h(v.y - bf16f(h1));
    unsigned l2 = bf16h(v.z - bf16f(h2)), l3 = bf16h(v.w - bf16f(h3));
    hi[i] = make_uint2(h0 | (h1 << 16), h2 | (h3 << 16));
    lo[i] = make_uint2(l0 | (l1 << 16), l2 | (l3 << 16));
}

// ---------------- zero buffer ----------------
__global__ void zero_kernel(float4* __restrict__ p, int n4) {
    int i = blockIdx.x * blockDim.x + threadIdx.x;
    if (i < n4) p[i] = make_float4(0.f, 0.f, 0.f, 0.f);
}

// ---------------- tensor-core GEMM (mma.sync bf16 3-term split), dual output set ----
// A pre-split bf16 hi/lo [n][k]; B pre-split [n][k]. Block tile 128x64, BK=32,
// 8 warps (4M x 2N), warp tile 32x32. blockIdx.y < nt1 -> set 1, else set 2.
#define GBM 128
#define GBN 64
#define GBK 32
#define AST 20   // smem row stride in u32 words (16 data + 4 pad)

__device__ __forceinline__ void mma_bf16(float* c, const unsigned* a, unsigned b0, unsigned b1) {
    asm volatile(
        "mma.sync.aligned.m16n8k16.row.col.f32.bf16.bf16.f32 "
        "{%0,%1,%2,%3}, {%4,%5,%6,%7}, {%8,%9}, {%0,%1,%2,%3};"
        : "+f"(c[0]), "+f"(c[1]), "+f"(c[2]), "+f"(c[3])
        : "r"(a[0]), "r"(a[1]), "r"(a[2]), "r"(a[3]), "r"(b0), "r"(b1));
}

__global__ __launch_bounds__(256, 2) void mma_gemm2_kernel(
    const unsigned short* __restrict__ Ah16, const unsigned short* __restrict__ Al16, int nrows,
    const unsigned short* __restrict__ B1h, const unsigned short* __restrict__ B1l,
    const float* __restrict__ bias1, float* __restrict__ C1, int ncols1, int nt1,
    const unsigned short* __restrict__ B2h, const unsigned short* __restrict__ B2l,
    const float* __restrict__ bias2, float* __restrict__ C2, int ncols2)
{
    __shared__ __align__(16) unsigned sAhi[GBM * AST];
    __shared__ __align__(16) unsigned sAlo[GBM * AST];
    __shared__ __align__(16) unsigned sBhi[GBN * AST];
    __shared__ __align__(16) unsigned sBlo[GBN * AST];

    const int tid  = threadIdx.x;
    const int lane = tid & 31;
    const int wid  = tid >> 5;
    const int g    = lane >> 2;
    const int t    = lane & 3;
    const int wm   = (wid & 3) * 32;
    const int wn   = (wid >> 2) * 32;
    const int row0 = blockIdx.x * GBM;

    // select output set
    int y = blockIdx.y;
    const uint4* Bh4; const uint4* Bl4; const float* bias; float* C; int ncols;
    if (y < nt1) { Bh4 = (const uint4*)B1h; Bl4 = (const uint4*)B1l; bias = bias1; C = C1; ncols = ncols1; }
    else { y -= nt1; Bh4 = (const uint4*)B2h; Bl4 = (const uint4*)B2l; bias = bias2; C = C2; ncols = ncols2; }
    const int col0 = y * GBN;

    const uint4* Ah4 = (const uint4*)Ah16;   // 16 uint4 per row (K=128 bf16)
    const uint4* Al4 = (const uint4*)Al16;

    // staging maps
    const int ar = tid >> 1;             // A row 0..127
    const int ah = tid & 1;              // 8-word half within 16-word chunk
    const int bn = tid >> 2;             // B n 0..63
    const int bw = tid & 3;              // uint4 within chunk

    const bool aok = (row0 + ar) < nrows;
    const size_t abase = (size_t)(row0 + ar) * 16 + ah * 2;
    const size_t bbase = (size_t)(col0 + bn) * 16 + bw;

    float acc[2][4][4];
#pragma unroll
    for (int i = 0; i < 2; i++)
#pragma unroll
        for (int j = 0; j < 4; j++)
#pragma unroll
            for (int q = 0; q < 4; q++) acc[i][j][q] = 0.f;

#pragma unroll
    for (int kc = 0; kc < HH; kc += GBK) {
        const int cu4 = kc >> 3;   // uint4 offset of this chunk within a row
        // ---- stage A (pure copy of pre-split bf16) ----
        {
            uint4 zero4 = make_uint4(0u, 0u, 0u, 0u);
            uint4 h0 = aok ? Ah4[abase + cu4]     : zero4;
            uint4 h1 = aok ? Ah4[abase + cu4 + 1] : zero4;
            uint4 l0 = aok ? Al4[abase + cu4]     : zero4;
            uint4 l1 = aok ? Al4[abase + cu4 + 1] : zero4;
            int sb = ar * AST + ah * 8;
            *(uint4*)&sAhi[sb]     = h0;
            *(uint4*)&sAhi[sb + 4] = h1;
            *(uint4*)&sAlo[sb]     = l0;
            *(uint4*)&sAlo[sb + 4] = l1;
        }
        // ---- stage B ----
        {
            uint4 h = Bh4[bbase + cu4];
            uint4 l = Bl4[bbase + cu4];
            int sb = bn * AST + bw * 4;
            *(uint4*)&sBhi[sb] = h;
            *(uint4*)&sBlo[sb] = l;
        }
        __syncthreads();

        // ---- compute: 2 k16 steps, 3-term split ----
#pragma unroll
        for (int s = 0; s < 2; s++) {
            unsigned ahi[2][4], alo[2][4];
#pragma unroll
            for (int ma = 0; ma < 2; ma++) {
                int b0 = (wm + ma * 16 + g) * AST + s * 8 + t;
                int b1 = (wm + ma * 16 + 8 + g) * AST + s * 8 + t;
                ahi[ma][0] = sAhi[b0];     ahi[ma][1] = sAhi[b1];
                ahi[ma][2] = sAhi[b0 + 4]; ahi[ma][3] = sAhi[b1 + 4];
                alo[ma][0] = sAlo[b0];     alo[ma][1] = sAlo[b1];
                alo[ma][2] = sAlo[b0 + 4]; alo[ma][3] = sAlo[b1 + 4];
            }
#pragma unroll
            for (int na = 0; na < 4; na++) {
                int bb = (wn + na * 8 + g) * AST + s * 8 + t;
                unsigned bh0 = sBhi[bb], bh1 = sBhi[bb + 4];
                unsigned bl0 = sBlo[bb], bl1 = sBlo[bb + 4];
#pragma unroll
                for (int ma = 0; ma < 2; ma++) {
                    mma_bf16(acc[ma][na], ahi[ma], bh0, bh1);
                    mma_bf16(acc[ma][na], ahi[ma], bl0, bl1);
                    mma_bf16(acc[ma][na], alo[ma], bh0, bh1);
                }
            }
        }
        __syncthreads();
    }

    // ---- epilogue ----
#pragma unroll
    for (int ma = 0; ma < 2; ma++) {
#pragma unroll
        for (int na = 0; na < 4; na++) {
            int col = col0 + wn + na * 8 + t * 2;
            float b0 = bias ? bias[col] : 0.f;
            float b1 = bias ? bias[col + 1] : 0.f;
            int r0 = row0 + wm + ma * 16 + g;
            if (r0 < nrows) {
                float2 o = make_float2(acc[ma][na][0] + b0, acc[ma][na][1] + b1);
                *(float2*)&C[(size_t)r0 * ncols + col] = o;
            }
            int r1 = r0 + 8;
            if (r1 < nrows) {
                float2 o = make_float2(acc[ma][na][2] + b0, acc[ma][na][3] + b1);
                *(float2*)&C[(size_t)r1 * ncols + col] = o;
            }
        }
    }
}

// ---------------- edge gather * weight -> vector red scatter-add ----------------
__global__ __launch_bounds__(256) void edge_scatter_kernel(
    const float* __restrict__ m, const float* __restrict__ ew,
    const int* __restrict__ src, const int* __restrict__ dst,
    float* __restrict__ agg)
{
    long long gid = (long long)blockIdx.x * blockDim.x + threadIdx.x;
    int edge = (int)(gid >> 5);
    int lane = (int)(gid & 31);
    if (edge >= EE) return;

    int s = src[edge];
    int d = dst[edge];
    float w = ew[edge];

    float4 v = *(const float4*)(m + (size_t)s * HH + lane * 4);
    v.x *= w; v.y *= w; v.z *= w; v.w *= w;

    float* dstp = agg + (size_t)d * HH + lane * 4;
    asm volatile("red.global.add.v4.f32 [%0], {%1, %2, %3, %4};"
                 :: "l"(dstp), "f"(v.x), "f"(v.y), "f"(v.z), "f"(v.w)
                 : "memory");
}

// ---------------- GRU elementwise ----------------
__global__ __launch_bounds__(256) void gru_elem_kernel(
    const float* __restrict__ gi, const float* __restrict__ gh,
    const float* __restrict__ x, float* __restrict__ xout, int n4)
{
    int idx = blockIdx.x * blockDim.x + threadIdx.x;
    if (idx >= n4) return;
    int node = idx >> 5;
    int c4   = idx & 31;

    const float4* gi4 = (const float4*)gi;
    const float4* gh4 = (const float4*)gh;
    size_t base = (size_t)node * 96 + c4;

    float4 ir = gi4[base];
    float4 iz = gi4[base + 32];
    float4 in_ = gi4[base + 64];
    float4 hr = gh4[base];
    float4 hz = gh4[base + 32];
    float4 hn = gh4[base + 64];
    float4 xv = ((const float4*)x)[idx];

    float4 o;
    {
        float r  = 1.f / (1.f + __expf(-(ir.x + hr.x)));
        float zg = 1.f / (1.f + __expf(-(iz.x + hz.x)));
        float nn = tanhf(in_.x + r * hn.x);
        o.x = (1.f - zg) * nn + zg * xv.x;
    }
    {
        float r  = 1.f / (1.f + __expf(-(ir.y + hr.y)));
        float zg = 1.f / (1.f + __expf(-(iz.y + hz.y)));
        float nn = tanhf(in_.y + r * hn.y);
        o.y = (1.f - zg) * nn + zg * xv.y;
    }
    {
        float r  = 1.f / (1.f + __expf(-(ir.z + hr.z)));
        float zg = 1.f / (1.f + __expf(-(iz.z + hz.z)));
        float nn = tanhf(in_.z + r * hn.z);
        o.z = (1.f - zg) * nn + zg * xv.z;
    }
    {
        float r  = 1.f / (1.f + __expf(-(ir.w + hr.w)));
        float zg = 1.f / (1.f + __expf(-(iz.w + hz.w)));
        float nn = tanhf(in_.w + r * hn.w);
        o.w = (1.f - zg) * nn + zg * xv.w;
    }
    ((float4*)xout)[idx] = o;
}

// ---------------- host ----------------
extern "C" void kernel_launch(void* const* d_in, const int* in_sizes, int n_in,
                              void* d_out, int out_size)
{
    const float* z = nullptr; const float* ew = nullptr; const void* ei = nullptr;
    const float* mats[3] = {nullptr, nullptr, nullptr}; int nmat = 0;
    const float* vecs[2] = {nullptr, nullptr};          int nvec = 0;
    for (int i = 0; i < n_in; i++) {
        int sz = in_sizes[i];
        if      (sz == NN * HH)      z  = (const float*)d_in[i];
        else if (sz == EE)           ew = (const float*)d_in[i];
        else if (sz == 2 * EE)       ei = d_in[i];
        else if (sz == 3 * HH * HH) { if (nmat < 3) mats[nmat++] = (const float*)d_in[i]; }
        else if (sz == 3 * HH)      { if (nvec < 2) vecs[nvec++] = (const float*)d_in[i]; }
    }
    if (!z  && n_in > 0) z  = (const float*)d_in[0];
    if (!ew && n_in > 1) ew = (const float*)d_in[1];
    if (nmat < 3) { mats[0] = (const float*)d_in[2]; mats[1] = (const float*)d_in[3]; mats[2] = (const float*)d_in[4]; }
    if (nvec < 2) { vecs[0] = (const float*)d_in[5]; vecs[1] = (const float*)d_in[6]; }
    if (!ei && n_in > 7) ei = d_in[7];

    const float* weight = mats[0];
    const float* w_ih   = mats[1];
    const float* w_hh   = mats[2];
    const float* b_ih   = vecs[0];
    const float* b_hh   = vecs[1];
    float*       out    = (float*)d_out;

    float *pm, *pagg, *pgi, *pgh, *px;
    unsigned short *pB1h, *pB1l, *pIhh, *pIhl, *pHhh, *pHhl;
    unsigned short *pxh, *pxl, *pah, *pal;
    int *psrc, *pdst;
    cudaGetSymbolAddress((void**)&pm,   g_m);
    cudaGetSymbolAddress((void**)&pagg, g_agg);
    cudaGetSymbolAddress((void**)&pgi,  g_gi);
    cudaGetSymbolAddress((void**)&pgh,  g_gh);
    cudaGetSymbolAddress((void**)&px,   g_x);
    cudaGetSymbolAddress((void**)&pB1h, g_B1hi);
    cudaGetSymbolAddress((void**)&pB1l, g_B1lo);
    cudaGetSymbolAddress((void**)&pIhh, g_Bihhi);
    cudaGetSymbolAddress((void**)&pIhl, g_Bihlo);
    cudaGetSymbolAddress((void**)&pHhh, g_Bhhhi);
    cudaGetSymbolAddress((void**)&pHhl, g_Bhhlo);
    cudaGetSymbolAddress((void**)&pxh,  g_xhi);
    cudaGetSymbolAddress((void**)&pxl,  g_xlo);
    cudaGetSymbolAddress((void**)&pah,  g_ahi);
    cudaGetSymbolAddress((void**)&pal,  g_alo);
    cudaGetSymbolAddress((void**)&psrc, g_src);
    cudaGetSymbolAddress((void**)&pdst, g_dst);

    const int GMX = (NN + GBM - 1) / GBM;             // 782
    const int n4  = NN * (HH / 4);
    const int zgrid = (n4 + 255) / 256;
    const long long ethreads = (long long)EE * 32;
    const int egrid = (int)((ethreads + 255) / 256);

    detect_idx_kernel<<<1, 256>>>((const int*)ei);
    prep_idx_kernel<<<(EE + 255) / 256, 256>>>(ei, psrc, pdst);
    split_w1_kernel<<<(3 * HH * HH + 255) / 256, 256>>>(weight, pB1h, pB1l);
    split_w_kernel<<<(H3 * HH + 255) / 256, 256>>>(w_ih, H3 * HH, pIhh, pIhl);
    split_w_kernel<<<(H3 * HH + 255) / 256, 256>>>(w_hh, H3 * HH, pHhh, pHhl);

    const float* x = z;
    for (int l = 0; l < LL; l++) {
        // split x once (consumed by both fused-output GEMM sets)
        split_act_kernel<<<zgrid, 256>>>((const float4*)x, n4, (uint2*)pxh, (uint2*)pxl);
        // fused: m = x@W[l] (set1, 2 tiles) and gh = x@w_hh^T + b_hh (set2, 6 tiles)
        mma_gemm2_kernel<<<dim3(GMX, 8), 256>>>(
            pxh, pxl, NN,
            pB1h + (size_t)l * HH * HH, pB1l + (size_t)l * HH * HH, nullptr, pm, HH, 2,
            pHhh, pHhl, b_hh, pgh, H3);
        // agg = segment_sum(m[src] * ew, dst)
        zero_kernel<<<zgrid, 256>>>((float4*)pagg, n4);
        edge_scatter_kernel<<<egrid, 256>>>(pm, ew, psrc, pdst, pagg);
        // split agg, then gi = agg@w_ih^T + b_ih
        split_act_kernel<<<zgrid, 256>>>((const float4*)pagg, n4, (uint2*)pah, (uint2*)pal);
        mma_gemm2_kernel<<<dim3(GMX, 6), 256>>>(
            pah, pal, NN,
            pIhh, pIhl, b_ih, pgi, H3, 6,
            pIhh, pIhl, b_ih, pgi, H3);
        // GRU elementwise
        float* xout = (l == LL - 1) ? out : px;
        gru_elem_kernel<<<zgrid, 256>>>(pgi, pgh, x, xout, n4);
        x = px;
    }
}

// round 13
// speedup vs baseline: 1.9766x; 1.0765x over previous
#include <cuda_runtime.h>
#include <cstdint>

#define NN 100000
#define EE 1600000
#define HH 128
#define H3 384
#define LL 3

// ---------------- scratch (static device globals; no allocation) ----------------
__device__ __align__(256) float g_m[(size_t)NN * HH];     // m = x @ W[l]
__device__ __align__(256) float g_agg[(size_t)NN * HH];   // scatter-add target
__device__ __align__(256) float g_gi[(size_t)NN * H3];    // agg @ w_ih^T + b_ih
__device__ __align__(256) float g_gh[(size_t)NN * H3];    // x   @ w_hh^T + b_hh
__device__ __align__(256) float g_x[(size_t)NN * HH];     // hidden state ping buffer
__device__ int g_idx64;
__device__ __align__(256) int g_src[EE];
__device__ __align__(256) int g_dst[EE];

// bf16 hi/lo split weights, stored [n][k] (k contiguous, K=128)
__device__ __align__(256) unsigned short g_B1hi[3 * HH * HH];
__device__ __align__(256) unsigned short g_B1lo[3 * HH * HH];
__device__ __align__(256) unsigned short g_Bihhi[H3 * HH];
__device__ __align__(256) unsigned short g_Bihlo[H3 * HH];
__device__ __align__(256) unsigned short g_Bhhhi[H3 * HH];
__device__ __align__(256) unsigned short g_Bhhlo[H3 * HH];

// ---------------- bf16 split helpers ----------------
__device__ __forceinline__ unsigned bf16h(float f) {
    unsigned x = __float_as_uint(f);
    return (x + 0x7fffu + ((x >> 16) & 1u)) >> 16;   // rn-even to bf16 bits
}
__device__ __forceinline__ float bf16f(unsigned b) { return __uint_as_float(b << 16); }

__device__ __forceinline__ uint32_t smem_u32(const void* p) {
    uint32_t a;
    asm("{ .reg .u64 t; cvta.to.shared.u64 t, %1; cvt.u32.u64 %0, t; }" : "=r"(a) : "l"(p));
    return a;
}
__device__ __forceinline__ void cpasync16(uint32_t dst, const void* src) {
    asm volatile("cp.async.cg.shared.global [%0], [%1], 16;" :: "r"(dst), "l"(src));
}
#define CP_COMMIT() asm volatile("cp.async.commit_group;" ::: "memory")
#define CP_WAIT1()  asm volatile("cp.async.wait_group 1;" ::: "memory")
#define CP_WAIT0()  asm volatile("cp.async.wait_group 0;" ::: "memory")

// ---------------- detect edge_index dtype ----------------
__global__ void detect_idx_kernel(const int* __restrict__ ei32) {
    int bad = 0;
    for (int i = threadIdx.x; i < 4096; i += blockDim.x)
        if ((i & 1) && ei32[i] != 0) bad = 1;
    bad = __syncthreads_or(bad);
    if (threadIdx.x == 0) g_idx64 = bad ? 0 : 1;
}

// ---------------- decode edge_index -> int32 src/dst ----------------
__global__ __launch_bounds__(256) void prep_idx_kernel(const void* __restrict__ ei,
                                                       int* __restrict__ src,
                                                       int* __restrict__ dst) {
    int e = blockIdx.x * blockDim.x + threadIdx.x;
    if (e >= EE) return;
    int s, d;
    if (g_idx64) {
        const long long* p = (const long long*)ei;
        s = (int)p[e]; d = (int)p[EE + e];
    } else {
        const int* p = (const int*)ei;
        s = p[e]; d = p[EE + e];
    }
    if ((unsigned)s >= NN) s = 0;
    if ((unsigned)d >= NN) d = 0;
    src[e] = s; dst[e] = d;
}

// ---------------- split weight[l] ([k][n]) -> transposed [n][k] hi/lo ----------------
__global__ void split_w1_kernel(const float* __restrict__ w,
                                unsigned short* __restrict__ hi,
                                unsigned short* __restrict__ lo) {
    int i = blockIdx.x * blockDim.x + threadIdx.x;
    if (i >= 3 * HH * HH) return;
    int l = i >> 14, rem = i & 16383;
    int k = rem >> 7, n = rem & 127;
    float f = w[i];
    unsigned h = bf16h(f);
    unsigned lb = bf16h(f - bf16f(h));
    int o = l * HH * HH + n * HH + k;
    hi[o] = (unsigned short)h;
    lo[o] = (unsigned short)lb;
}

// ---------------- elementwise split ([n][k] natural) ----------------
__global__ void split_w_kernel(const float* __restrict__ w, int count,
                               unsigned short* __restrict__ hi,
                               unsigned short* __restrict__ lo) {
    int i = blockIdx.x * blockDim.x + threadIdx.x;
    if (i >= count) return;
    float f = w[i];
    unsigned h = bf16h(f);
    hi[i] = (unsigned short)h;
    lo[i] = (unsigned short)bf16h(f - bf16f(h));
}

// ---------------- zero buffer ----------------
__global__ void zero_kernel(float4* __restrict__ p, int n4) {
    int i = blockIdx.x * blockDim.x + threadIdx.x;
    if (i < n4) p[i] = make_float4(0.f, 0.f, 0.f, 0.f);
}

// ---------------- persistent-A tensor GEMM (mma.sync bf16 3-term split) -------------
// A fp32 [nrows][128] staged ONCE per CTA as bf16 hi/lo; loops over all output
// column tiles of up to two (B, C, bias) sets. B pre-split bf16 [n][k].
// 8 warps (4M x 2N), warp tile 32x32, K=128 fully resident, cp.async dbl-buffered B.
#define SAW 68                       // smem row stride in words (64 data + 4 pad)
#define SA  (128 * SAW)              // 8704 words: one 128-row A array
#define SB  (64 * SAW)               // 4352 words: one 64-row B array
#define OFF_ALO SA
#define OFF_B   (2 * SA)
#define SMEM_WORDS (2 * SA + 4 * SB) // 34816
#define SMEM_BYTES (SMEM_WORDS * 4)  // 139264

__device__ __forceinline__ void mma_bf16(float* c, const unsigned* a, unsigned b0, unsigned b1) {
    asm volatile(
        "mma.sync.aligned.m16n8k16.row.col.f32.bf16.bf16.f32 "
        "{%0,%1,%2,%3}, {%4,%5,%6,%7}, {%8,%9}, {%0,%1,%2,%3};"
        : "+f"(c[0]), "+f"(c[1]), "+f"(c[2]), "+f"(c[3])
        : "r"(a[0]), "r"(a[1]), "r"(a[2]), "r"(a[3]), "r"(b0), "r"(b1));
}

__global__ __launch_bounds__(256) void mma_gemm_persist(
    const float* __restrict__ A, int nrows,
    const unsigned short* __restrict__ B1h, const unsigned short* __restrict__ B1l,
    const float* __restrict__ bias1, float* __restrict__ C1, int ncols1, int nt1,
    const unsigned short* __restrict__ B2h, const unsigned short* __restrict__ B2l,
    const float* __restrict__ bias2, float* __restrict__ C2, int ncols2, int nt2)
{
    extern __shared__ __align__(16) unsigned sm[];
    unsigned* sAhi = sm;
    unsigned* sAlo = sm + OFF_ALO;
    const uint32_t smb = smem_u32(sm);

    const int tid = threadIdx.x, lane = tid & 31, wid = tid >> 5;
    const int g = lane >> 2, t = lane & 3;
    const int wm = (wid & 3) * 32, wn = (wid >> 2) * 32;
    const int row0 = blockIdx.x * 128;
    const int NT = nt1 + nt2;

    // ---- stage A once: fp32 -> bf16 hi/lo (coalesced float4 rounds) ----
#pragma unroll
    for (int r = 0; r < 16; r++) {
        int i = r * 256 + tid;          // float4 index within 128x128 tile
        int row = i >> 5, q = i & 31;
        float4 v;
        if (row0 + row < nrows) v = *(const float4*)&A[(size_t)(row0 + row) * HH + q * 4];
        else v = make_float4(0.f, 0.f, 0.f, 0.f);
        unsigned h0 = bf16h(v.x), h1 = bf16h(v.y), h2 = bf16h(v.z), h3 = bf16h(v.w);
        unsigned l0 = bf16h(v.x - bf16f(h0)), l1 = bf16h(v.y - bf16f(h1));
        unsigned l2 = bf16h(v.z - bf16f(h2)), l3 = bf16h(v.w - bf16f(h3));
        int o = row * SAW + q * 2;
        sAhi[o] = h0 | (h1 << 16); sAhi[o + 1] = h2 | (h3 << 16);
        sAlo[o] = l0 | (l1 << 16); sAlo[o + 1] = l2 | (l3 << 16);
    }

    // B tile staging map: thread -> row tid>>2 (0..63), quarter tid&3 (4 uint4 each)
    const int brow = tid >> 2, bq = tid & 3;
    const uint32_t bdw = (uint32_t)(brow * SAW + bq * 16) * 4;   // byte offset within a B array

    auto issueB = [&](int ti) {
        const unsigned short* Bh; const unsigned short* Bl; int col0;
        if (ti < nt1) { Bh = B1h; Bl = B1l; col0 = ti * 64; }
        else          { Bh = B2h; Bl = B2l; col0 = (ti - nt1) * 64; }
        int buf = ti & 1;
        uint32_t dsth = smb + (uint32_t)(OFF_B + buf * 2 * SB) * 4 + bdw;
        uint32_t dstl = dsth + (uint32_t)SB * 4;
        const uint4* srch = (const uint4*)Bh + (size_t)(col0 + brow) * 16 + bq * 4;
        const uint4* srcl = (const uint4*)Bl + (size_t)(col0 + brow) * 16 + bq * 4;
#pragma unroll
        for (int j = 0; j < 4; j++) {
            cpasync16(dsth + j * 16, srch + j);
            cpasync16(dstl + j * 16, srcl + j);
        }
    };

    issueB(0); CP_COMMIT();

    for (int ti = 0; ti < NT; ti++) {
        bool has_next = (ti + 1 < NT);
        if (has_next) { issueB(ti + 1); CP_COMMIT(); }
        if (has_next) CP_WAIT1(); else CP_WAIT0();
        __syncthreads();

        const unsigned* bh = sm + OFF_B + (ti & 1) * 2 * SB;
        const unsigned* bl = bh + SB;

        float acc[2][4][4];
#pragma unroll
        for (int i = 0; i < 2; i++)
#pragma unroll
            for (int j = 0; j < 4; j++)
#pragma unroll
                for (int q = 0; q < 4; q++) acc[i][j][q] = 0.f;

#pragma unroll
        for (int s = 0; s < 8; s++) {
            unsigned ahi[2][4], alo[2][4];
#pragma unroll
            for (int ma = 0; ma < 2; ma++) {
                int b0 = (wm + ma * 16 + g) * SAW + s * 8 + t;
                int b1 = (wm + ma * 16 + 8 + g) * SAW + s * 8 + t;
                ahi[ma][0] = sAhi[b0];     ahi[ma][1] = sAhi[b1];
                ahi[ma][2] = sAhi[b0 + 4]; ahi[ma][3] = sAhi[b1 + 4];
                alo[ma][0] = sAlo[b0];     alo[ma][1] = sAlo[b1];
                alo[ma][2] = sAlo[b0 + 4]; alo[ma][3] = sAlo[b1 + 4];
            }
#pragma unroll
            for (int na = 0; na < 4; na++) {
                int bb = (wn + na * 8 + g) * SAW + s * 8 + t;
                unsigned bh0 = bh[bb], bh1 = bh[bb + 4];
                unsigned bl0 = bl[bb], bl1 = bl[bb + 4];
#pragma unroll
                for (int ma = 0; ma < 2; ma++) {
                    mma_bf16(acc[ma][na], ahi[ma], bh0, bh1);
                    mma_bf16(acc[ma][na], ahi[ma], bl0, bl1);
                    mma_bf16(acc[ma][na], alo[ma], bh0, bh1);
                }
            }
        }

        // ---- epilogue for this tile ----
        const float* bias; float* C; int ncols, col0;
        if (ti < nt1) { bias = bias1; C = C1; ncols = ncols1; col0 = ti * 64; }
        else          { bias = bias2; C = C2; ncols = ncols2; col0 = (ti - nt1) * 64; }
#pragma unroll
        for (int ma = 0; ma < 2; ma++) {
#pragma unroll
            for (int na = 0; na < 4; na++) {
                int col = col0 + wn + na * 8 + t * 2;
                float b0 = bias ? bias[col] : 0.f;
                float b1 = bias ? bias[col + 1] : 0.f;
                int r0 = row0 + wm + ma * 16 + g;
                if (r0 < nrows) {
                    float2 o = make_float2(acc[ma][na][0] + b0, acc[ma][na][1] + b1);
                    *(float2*)&C[(size_t)r0 * ncols + col] = o;
                }
                int r1 = r0 + 8;
                if (r1 < nrows) {
                    float2 o = make_float2(acc[ma][na][2] + b0, acc[ma][na][3] + b1);
                    *(float2*)&C[(size_t)r1 * ncols + col] = o;
                }
            }
        }
        __syncthreads();   // protect B buffer reuse before next issue
    }
}

// ---------------- edge gather * weight -> vector red scatter-add ----------------
__global__ __launch_bounds__(256) void edge_scatter_kernel(
    const float* __restrict__ m, const float* __restrict__ ew,
    const int* __restrict__ src, const int* __restrict__ dst,
    float* __restrict__ agg)
{
    long long gid = (long long)blockIdx.x * blockDim.x + threadIdx.x;
    int edge = (int)(gid >> 5);
    int lane = (int)(gid & 31);
    if (edge >= EE) return;

    int s = src[edge];
    int d = dst[edge];
    float w = ew[edge];

    float4 v = *(const float4*)(m + (size_t)s * HH + lane * 4);
    v.x *= w; v.y *= w; v.z *= w; v.w *= w;

    float* dstp = agg + (size_t)d * HH + lane * 4;
    asm volatile("red.global.add.v4.f32 [%0], {%1, %2, %3, %4};"
                 :: "l"(dstp), "f"(v.x), "f"(v.y), "f"(v.z), "f"(v.w)
                 : "memory");
}

// ---------------- GRU elementwise ----------------
__global__ __launch_bounds__(256) void gru_elem_kernel(
    const float* __restrict__ gi, const float* __restrict__ gh,
    const float* __restrict__ x, float* __restrict__ xout, int n4)
{
    int idx = blockIdx.x * blockDim.x + threadIdx.x;
    if (idx >= n4) return;
    int node = idx >> 5;
    int c4   = idx & 31;

    const float4* gi4 = (const float4*)gi;
    const float4* gh4 = (const float4*)gh;
    size_t base = (size_t)node * 96 + c4;

    float4 ir = gi4[base];
    float4 iz = gi4[base + 32];
    float4 in_ = gi4[base + 64];
    float4 hr = gh4[base];
    float4 hz = gh4[base + 32];
    float4 hn = gh4[base + 64];
    float4 xv = ((const float4*)x)[idx];

    float4 o;
    {
        float r  = 1.f / (1.f + __expf(-(ir.x + hr.x)));
        float zg = 1.f / (1.f + __expf(-(iz.x + hz.x)));
        float nn = tanhf(in_.x + r * hn.x);
        o.x = (1.f - zg) * nn + zg * xv.x;
    }
    {
        float r  = 1.f / (1.f + __expf(-(ir.y + hr.y)));
        float zg = 1.f / (1.f + __expf(-(iz.y + hz.y)));
        float nn = tanhf(in_.y + r * hn.y);
        o.y = (1.f - zg) * nn + zg * xv.y;
    }
    {
        float r  = 1.f / (1.f + __expf(-(ir.z + hr.z)));
        float zg = 1.f / (1.f + __expf(-(iz.z + hz.z)));
        float nn = tanhf(in_.z + r * hn.z);
        o.z = (1.f - zg) * nn + zg * xv.z;
    }
    {
        float r  = 1.f / (1.f + __expf(-(ir.w + hr.w)));
        float zg = 1.f / (1.f + __expf(-(iz.w + hz.w)));
        float nn = tanhf(in_.w + r * hn.w);
        o.w = (1.f - zg) * nn + zg * xv.w;
    }
    ((float4*)xout)[idx] = o;
}

// ---------------- host ----------------
extern "C" void kernel_launch(void* const* d_in, const int* in_sizes, int n_in,
                              void* d_out, int out_size)
{
    const float* z = nullptr; const float* ew = nullptr; const void* ei = nullptr;
    const float* mats[3] = {nullptr, nullptr, nullptr}; int nmat = 0;
    const float* vecs[2] = {nullptr, nullptr};          int nvec = 0;
    for (int i = 0; i < n_in; i++) {
        int sz = in_sizes[i];
        if      (sz == NN * HH)      z  = (const float*)d_in[i];
        else if (sz == EE)           ew = (const float*)d_in[i];
        else if (sz == 2 * EE)       ei = d_in[i];
        else if (sz == 3 * HH * HH) { if (nmat < 3) mats[nmat++] = (const float*)d_in[i]; }
        else if (sz == 3 * HH)      { if (nvec < 2) vecs[nvec++] = (const float*)d_in[i]; }
    }
    if (!z  && n_in > 0) z  = (const float*)d_in[0];
    if (!ew && n_in > 1) ew = (const float*)d_in[1];
    if (nmat < 3) { mats[0] = (const float*)d_in[2]; mats[1] = (const float*)d_in[3]; mats[2] = (const float*)d_in[4]; }
    if (nvec < 2) { vecs[0] = (const float*)d_in[5]; vecs[1] = (const float*)d_in[6]; }
    if (!ei && n_in > 7) ei = d_in[7];

    const float* weight = mats[0];
    const float* w_ih   = mats[1];
    const float* w_hh   = mats[2];
    const float* b_ih   = vecs[0];
    const float* b_hh   = vecs[1];
    float*       out    = (float*)d_out;

    float *pm, *pagg, *pgi, *pgh, *px;
    unsigned short *pB1h, *pB1l, *pIhh, *pIhl, *pHhh, *pHhl;
    int *psrc, *pdst;
    cudaGetSymbolAddress((void**)&pm,   g_m);
    cudaGetSymbolAddress((void**)&pagg, g_agg);
    cudaGetSymbolAddress((void**)&pgi,  g_gi);
    cudaGetSymbolAddress((void**)&pgh,  g_gh);
    cudaGetSymbolAddress((void**)&px,   g_x);
    cudaGetSymbolAddress((void**)&pB1h, g_B1hi);
    cudaGetSymbolAddress((void**)&pB1l, g_B1lo);
    cudaGetSymbolAddress((void**)&pIhh, g_Bihhi);
    cudaGetSymbolAddress((void**)&pIhl, g_Bihlo);
    cudaGetSymbolAddress((void**)&pHhh, g_Bhhhi);
    cudaGetSymbolAddress((void**)&pHhl, g_Bhhlo);
    cudaGetSymbolAddress((void**)&psrc, g_src);
    cudaGetSymbolAddress((void**)&pdst, g_dst);

    // set once on the first (uncaptured correctness) call; graph replays inherit it
    static int smem_set = 0;
    if (!smem_set) {
        cudaFuncSetAttribute(mma_gemm_persist, cudaFuncAttributeMaxDynamicSharedMemorySize, SMEM_BYTES);
        smem_set = 1;
    }

    const int GMX = (NN + 127) / 128;                 // 782
    const int n4  = NN * (HH / 4);
    const int zgrid = (n4 + 255) / 256;
    const long long ethreads = (long long)EE * 32;
    const int egrid = (int)((ethreads + 255) / 256);

    detect_idx_kernel<<<1, 256>>>((const int*)ei);
    prep_idx_kernel<<<(EE + 255) / 256, 256>>>(ei, psrc, pdst);
    split_w1_kernel<<<(3 * HH * HH + 255) / 256, 256>>>(weight, pB1h, pB1l);
    split_w_kernel<<<(H3 * HH + 255) / 256, 256>>>(w_ih, H3 * HH, pIhh, pIhl);
    split_w_kernel<<<(H3 * HH + 255) / 256, 256>>>(w_hh, H3 * HH, pHhh, pHhl);

    const float* x = z;
    for (int l = 0; l < LL; l++) {
        // fused: m = x@W[l] (2 tiles) and gh = x@w_hh^T + b_hh (6 tiles); A staged once
        mma_gemm_persist<<<GMX, 256, SMEM_BYTES>>>(
            x, NN,
            pB1h + (size_t)l * HH * HH, pB1l + (size_t)l * HH * HH, nullptr, pm, HH, 2,
            pHhh, pHhl, b_hh, pgh, H3, 6);
        // agg = segment_sum(m[src] * ew, dst)
        zero_kernel<<<zgrid, 256>>>((float4*)pagg, n4);
        edge_scatter_kernel<<<egrid, 256>>>(pm, ew, psrc, pdst, pagg);
        // gi = agg @ w_ih^T + b_ih (6 tiles)
        mma_gemm_persist<<<GMX, 256, SMEM_BYTES>>>(
            pagg, NN,
            pIhh, pIhl, b_ih, pgi, H3, 6,
            nullptr, nullptr, nullptr, nullptr, 0, 0);
        // GRU elementwise
        float* xout = (l == LL - 1) ? out : px;
        gru_elem_kernel<<<zgrid, 256>>>(pgi, pgh, x, xout, n4);
        x = px;
    }
}